// round 6
// baseline (speedup 1.0000x reference)
#include <cuda_runtime.h>

#define N_CELLS 100000
#define N_ISO   16
#define KP1     31
#define WARPS_PER_BLOCK 8
#define THREADS (WARPS_PER_BLOCK * 32)
#define GRID    888                      /* 148 SMs x 6 blocks/SM -> one resident wave */
#define TOTAL_WARPS (GRID * WARPS_PER_BLOCK)
#define ROW4    8                        /* packed row = 8 float4 = 128B (one L2 line) */

/* Packed rows: [u, s0..s15, 0,0,...,0] (17 live floats, 15 zeros). float4-typed for alignment. */
__device__ float4       g_packS[(size_t)N_CELLS * ROW4];
__device__ float4       g_packP[(size_t)N_CELLS * ROW4];
__device__ float        g_partials[GRID];
__device__ unsigned int g_ticket = 0;

__global__ void pack_kernel(const float* __restrict__ u,
                            const float* __restrict__ s,
                            const float* __restrict__ up,
                            const float* __restrict__ sp)
{
    const int t = blockIdx.x * blockDim.x + threadIdx.x;
    if (t >= N_CELLS * ROW4) return;
    const int cell = t >> 3;
    const int k    = t & 7;

    float4 vs = make_float4(0.f, 0.f, 0.f, 0.f);
    float4 vp = vs;
    const size_t sb = (size_t)cell * N_ISO;

    if (k == 0) {
        vs = make_float4(u[cell],  s[sb+0],  s[sb+1],  s[sb+2]);
        vp = make_float4(up[cell], sp[sb+0], sp[sb+1], sp[sb+2]);
    } else if (k <= 3) {
        const int m = 4 * k - 1;                 /* floats 4k..4k+3 = s[m..m+3] */
        vs = make_float4(s[sb+m],  s[sb+m+1],  s[sb+m+2],  s[sb+m+3]);
        vp = make_float4(sp[sb+m], sp[sb+m+1], sp[sb+m+2], sp[sb+m+3]);
    } else if (k == 4) {
        vs.x = s[sb+15];
        vp.x = sp[sb+15];
    }
    g_packS[(size_t)cell * ROW4 + k] = vs;
    g_packP[(size_t)cell * ROW4 + k] = vp;
}

__global__ __launch_bounds__(THREADS, 6) void cost_kernel(
    const int* __restrict__ idx,
    float* __restrict__ out)
{
    const int warp  = threadIdx.x >> 5;
    const int lane  = threadIdx.x & 31;
    const int gwarp = blockIdx.x * WARPS_PER_BLOCK + warp;
    const int r     = lane & 7;          /* 16B slice within the 128B row */
    const int g     = lane >> 3;         /* neighbor sub-slot (0..3) per batch */

    __shared__ float ws[WARPS_PER_BLOCK];
    __shared__ int   s_islast;

    float lsum = 0.0f;

    for (int cell = gwarp; cell < N_CELLS; cell += TOTAL_WARPS) {
        /* Own packed row: 32 lanes cover one 128B line twice (S and P) -> 2 wavefronts. */
        const float4 a = g_packS[(size_t)cell * ROW4 + r];
        const float4 b = g_packP[(size_t)cell * ROW4 + r];
        /* Slice of v: r=0 lane's .x is uv; pad slices are exactly zero. */
        const float sv0 = b.x - a.x, sv1 = b.y - a.y, sv2 = b.z - a.z, sv3 = b.w - a.w;

        float pv = sv0*sv0 + sv1*sv1 + sv2*sv2 + sv3*sv3;
        pv += __shfl_xor_sync(0xffffffffu, pv, 1);
        pv += __shfl_xor_sync(0xffffffffu, pv, 2);
        pv += __shfl_xor_sync(0xffffffffu, pv, 4);
        const float vsq = pv;            /* |v|^2 in every lane of each 8-group */

        int my_idx = 0;
        if (lane < KP1 - 1) my_idx = idx[(size_t)cell * KP1 + 1 + lane];

        float cmax = -3.0e38f;

        #pragma unroll
        for (int bt = 0; bt < 8; bt++) {
            const int slot = bt * 4 + g;                            /* neighbor 0..31 */
            const int j    = __shfl_sync(0xffffffffu, my_idx, slot);

            /* Unpredicated gather: 4 rows x 8 lanes, each row = ONE 128B line. */
            const float4 nr = g_packS[(size_t)j * ROW4 + r];
            const float d0 = nr.x - a.x, d1 = nr.y - a.y, d2 = nr.z - a.z, d3 = nr.w - a.w;

            float pdot = sv0*d0 + sv1*d1 + sv2*d2 + sv3*d3;
            float pnsq = d0*d0 + d1*d1 + d2*d2 + d3*d3;

            pdot += __shfl_xor_sync(0xffffffffu, pdot, 1);
            pdot += __shfl_xor_sync(0xffffffffu, pdot, 2);
            pdot += __shfl_xor_sync(0xffffffffu, pdot, 4);
            pnsq += __shfl_xor_sync(0xffffffffu, pnsq, 1);
            pnsq += __shfl_xor_sync(0xffffffffu, pnsq, 2);
            pnsq += __shfl_xor_sync(0xffffffffu, pnsq, 4);

            if (r == 0 && slot < KP1 - 1) {
                const float den2 = vsq * pnsq;
                const float cosv = (den2 > 0.0f) ? pdot * rsqrtf(den2) : pdot;
                cmax = fmaxf(cmax, cosv);
            }
        }

        /* Warp max over the 4 group leaders (others hold the sentinel). */
        #pragma unroll
        for (int o = 16; o > 0; o >>= 1)
            cmax = fmaxf(cmax, __shfl_xor_sync(0xffffffffu, cmax, o));

        if (lane == 0) lsum += 1.0f - cmax;
    }

    if (lane == 0) ws[warp] = lsum;
    __syncthreads();

    if (threadIdx.x == 0) {
        float bsum = 0.0f;
        #pragma unroll
        for (int w = 0; w < WARPS_PER_BLOCK; w++) bsum += ws[w];
        g_partials[blockIdx.x] = bsum;
        __threadfence();
        const unsigned t = atomicInc(&g_ticket, GRID - 1);  /* wraps -> graph-replay safe */
        s_islast = (t == GRID - 1);
    }
    __syncthreads();

    if (s_islast) {
        float psum = 0.0f;
        const volatile float* vp = g_partials;
        for (int i = threadIdx.x; i < GRID; i += THREADS) psum += vp[i];
        #pragma unroll
        for (int o = 16; o > 0; o >>= 1)
            psum += __shfl_xor_sync(0xffffffffu, psum, o);
        if (lane == 0) ws[warp] = psum;
        __syncthreads();
        if (threadIdx.x == 0) {
            float total = 0.0f;
            #pragma unroll
            for (int w = 0; w < WARPS_PER_BLOCK; w++) total += ws[w];
            out[0] = total * (1.0f / (float)N_CELLS);
        }
    }
}

extern "C" void kernel_launch(void* const* d_in, const int* in_sizes, int n_in,
                              void* d_out, int out_size) {
    const float* u   = (const float*)d_in[0];
    const float* s   = (const float*)d_in[1];
    const float* up  = (const float*)d_in[2];
    const float* sp  = (const float*)d_in[3];
    const int*   idx = (const int*)d_in[4];
    float* out = (float*)d_out;

    const int pack_grid = (N_CELLS * ROW4 + 255) / 256;
    pack_kernel<<<pack_grid, 256>>>(u, s, up, sp);
    cost_kernel<<<GRID, THREADS>>>(idx, out);
}

// round 7
// speedup vs baseline: 1.7810x; 1.7810x over previous
#include <cuda_runtime.h>

#define N_CELLS 100000
#define N_ISO   16
#define KP1     31
#define WARPS_PER_BLOCK 8
#define THREADS (WARPS_PER_BLOCK * 32)
#define BLOCKS_PER_SM 5
#define GRID    (148 * BLOCKS_PER_SM)    /* 740: one exact resident wave */
#define TOTAL_WARPS (GRID * WARPS_PER_BLOCK)

__device__ float        g_partials[GRID];
__device__ unsigned int g_ticket = 0;

__global__ __launch_bounds__(THREADS, BLOCKS_PER_SM) void cost_kernel(
    const float* __restrict__ u,
    const float* __restrict__ s,
    const float* __restrict__ up,
    const float* __restrict__ sp,
    const int*   __restrict__ idx,
    float* __restrict__ out)
{
    const int warp    = threadIdx.x >> 5;
    const int lane    = threadIdx.x & 31;
    const int gwarp   = blockIdx.x * WARPS_PER_BLOCK + warp;
    const int chunk   = lane & 3;        /* 16B chunk of a 64B s-row */
    const int nb_base = lane >> 2;       /* neighbor sub-slot within a batch (0..7) */

    __shared__ float ws[WARPS_PER_BLOCK];
    __shared__ int   s_islast;

    float lsum = 0.0f;

    for (int cell = gwarp; cell < N_CELLS; cell += TOTAL_WARPS) {
        /* Cell-own data (broadcast addresses). */
        const float ui = u[cell];
        const float uv = up[cell] - ui;

        const float4 a = reinterpret_cast<const float4*>(s  + (size_t)cell * N_ISO)[chunk];
        const float4 b = reinterpret_cast<const float4*>(sp + (size_t)cell * N_ISO)[chunk];
        const float sv0 = b.x - a.x, sv1 = b.y - a.y, sv2 = b.z - a.z, sv3 = b.w - a.w;

        float pv = sv0*sv0 + sv1*sv1 + sv2*sv2 + sv3*sv3;
        pv += __shfl_xor_sync(0xffffffffu, pv, 1);
        pv += __shfl_xor_sync(0xffffffffu, pv, 2);
        const float vsq = fmaf(uv, uv, pv);

        /* Per-lane neighbor index + u value (coalesced idx; u gather in flight early). */
        int   my_idx = 0;
        float my_un  = 0.0f;
        if (lane < KP1 - 1) {
            my_idx = idx[(size_t)cell * KP1 + 1 + lane];
            my_un  = u[my_idx] - ui;
        }

        /* ---- Issue ALL broadcasts and ALL four gather loads up front (MLP=4). ---- */
        int   j0, j1, j2, j3;
        float un0, un1, un2, un3;
        j0  = __shfl_sync(0xffffffffu, my_idx, 0  + nb_base);
        j1  = __shfl_sync(0xffffffffu, my_idx, 8  + nb_base);
        j2  = __shfl_sync(0xffffffffu, my_idx, 16 + nb_base);
        j3  = __shfl_sync(0xffffffffu, my_idx, 24 + nb_base);
        un0 = __shfl_sync(0xffffffffu, my_un,  0  + nb_base);
        un1 = __shfl_sync(0xffffffffu, my_un,  8  + nb_base);
        un2 = __shfl_sync(0xffffffffu, my_un,  16 + nb_base);
        un3 = __shfl_sync(0xffffffffu, my_un,  24 + nb_base);

        const float4 nr0 = reinterpret_cast<const float4*>(s + (size_t)j0 * N_ISO)[chunk];
        const float4 nr1 = reinterpret_cast<const float4*>(s + (size_t)j1 * N_ISO)[chunk];
        const float4 nr2 = reinterpret_cast<const float4*>(s + (size_t)j2 * N_ISO)[chunk];
        const float4 nr3 = reinterpret_cast<const float4*>(s + (size_t)j3 * N_ISO)[chunk];

        float cmax = -3.0e38f;

        /* ---- Consume the four batches (loads already in flight). ---- */
        #pragma unroll
        for (int bt = 0; bt < 4; bt++) {
            const float4 nr = (bt == 0) ? nr0 : (bt == 1) ? nr1 : (bt == 2) ? nr2 : nr3;
            const float  un = (bt == 0) ? un0 : (bt == 1) ? un1 : (bt == 2) ? un2 : un3;
            const int   slot = bt * 8 + nb_base;

            const float d0 = nr.x - a.x, d1 = nr.y - a.y, d2 = nr.z - a.z, d3 = nr.w - a.w;

            float pdot = sv0*d0 + sv1*d1 + sv2*d2 + sv3*d3;
            float pnsq = d0*d0 + d1*d1 + d2*d2 + d3*d3;

            pdot += __shfl_xor_sync(0xffffffffu, pdot, 1);
            pdot += __shfl_xor_sync(0xffffffffu, pdot, 2);
            pnsq += __shfl_xor_sync(0xffffffffu, pnsq, 1);
            pnsq += __shfl_xor_sync(0xffffffffu, pnsq, 2);

            if (chunk == 0 && slot < KP1 - 1) {
                const float dot  = fmaf(uv, un, pdot);
                const float nsq  = fmaf(un, un, pnsq);
                const float den2 = vsq * nsq;
                const float cosv = (den2 > 0.0f) ? dot * rsqrtf(den2) : dot;
                cmax = fmaxf(cmax, cosv);
            }
        }

        /* Warp max over the 30 leader cosines. */
        #pragma unroll
        for (int o = 16; o > 0; o >>= 1)
            cmax = fmaxf(cmax, __shfl_xor_sync(0xffffffffu, cmax, o));

        if (lane == 0) lsum += 1.0f - cmax;
    }

    if (lane == 0) ws[warp] = lsum;
    __syncthreads();

    if (threadIdx.x == 0) {
        float bsum = 0.0f;
        #pragma unroll
        for (int w = 0; w < WARPS_PER_BLOCK; w++) bsum += ws[w];
        g_partials[blockIdx.x] = bsum;
        __threadfence();
        const unsigned t = atomicInc(&g_ticket, GRID - 1);  /* wraps -> graph-replay safe */
        s_islast = (t == GRID - 1);
    }
    __syncthreads();

    if (s_islast) {
        float psum = 0.0f;
        const volatile float* vp = g_partials;
        for (int i = threadIdx.x; i < GRID; i += THREADS) psum += vp[i];
        #pragma unroll
        for (int o = 16; o > 0; o >>= 1)
            psum += __shfl_xor_sync(0xffffffffu, psum, o);
        if (lane == 0) ws[warp] = psum;
        __syncthreads();
        if (threadIdx.x == 0) {
            float total = 0.0f;
            #pragma unroll
            for (int w = 0; w < WARPS_PER_BLOCK; w++) total += ws[w];
            out[0] = total * (1.0f / (float)N_CELLS);
        }
    }
}

extern "C" void kernel_launch(void* const* d_in, const int* in_sizes, int n_in,
                              void* d_out, int out_size) {
    const float* u   = (const float*)d_in[0];
    const float* s   = (const float*)d_in[1];
    const float* up  = (const float*)d_in[2];
    const float* sp  = (const float*)d_in[3];
    const int*   idx = (const int*)d_in[4];
    float* out = (float*)d_out;

    cost_kernel<<<GRID, THREADS>>>(u, s, up, sp, idx, out);
}